// round 1
// baseline (speedup 1.0000x reference)
#include <cuda_runtime.h>
#include <math.h>
#include <stdint.h>

#define NTOK 16384      // 8*2048 tokens
#define DMODEL 1024
#define NHEAD 16
#define HDIM 64
#define NEXP 64
#define DGATE 256

// ---------------- scratch (static device globals; no allocation) ----------------
__device__ float g_kvpart[8][64 * 2048];        // partial k|v sums over d-chunks
__device__ float g_kv[64 * 2048];               // [e][0..1023]=k, [1024..2047]=v (bias folded)
__device__ float g_Wscore[1024 * 1024];         // [d][he]
__device__ float g_cvec[1024];                  // [he]
__device__ float g_Bmat[1024 * 1024];           // [he][dout]
__device__ float g_w1t[1024 * 256];             // gate_w1 transposed [d][j]
__device__ float g_w2t[256 * 64];               // gate_w2 transposed [j][e]
__device__ float g_S[(size_t)NTOK * 1024];      // scores -> attn (in place)
__device__ float g_P[(size_t)NTOK * 1024];      // attn_out
__device__ float g_Hb[(size_t)NTOK * 256];      // gate hidden

// ---------------- f32x2 helpers (FFMA2, Blackwell packed fp32) ----------------
__device__ __forceinline__ unsigned long long pk2(float lo, float hi) {
    unsigned long long r;
    asm("mov.b64 %0, {%1, %2};" : "=l"(r) : "f"(lo), "f"(hi));
    return r;
}
__device__ __forceinline__ unsigned long long ffma2(unsigned long long a, unsigned long long b,
                                                    unsigned long long c) {
    unsigned long long d;
    asm("fma.rn.f32x2 %0, %1, %2, %3;" : "=l"(d) : "l"(a), "l"(b), "l"(c));
    return d;
}
__device__ __forceinline__ void upk2(unsigned long long v, float& lo, float& hi) {
    asm("mov.b64 {%0, %1}, %2;" : "=f"(lo), "=f"(hi) : "l"(v));
}

__device__ __forceinline__ float gelu_exact(float x) {
    return 0.5f * x * (1.0f + erff(x * 0.70710678118654752f));
}

// ---------------- precompute kernels ----------------

// k|v partials: part[dc][e*2048 + i] = sum_{d in chunk dc} emb[e][d] * in_proj_w[1024+i][d]
// grid (8 ichunk, 8 dchunk), 256 threads
__global__ void kv_part_kernel(const float* __restrict__ w_in, const float* __restrict__ emb) {
    int ic = blockIdx.x, dc = blockIdx.y;
    int i = ic * 256 + threadIdx.x;   // [0,2048): 0..1023 -> k rows, 1024..2047 -> v rows
    __shared__ float es[64][132];     // [e][d_local], 132 keeps 16B alignment per row
    for (int idx = threadIdx.x; idx < 64 * 128; idx += 256) {
        int e = idx >> 7, dl = idx & 127;
        es[e][dl] = emb[e * 1024 + dc * 128 + dl];
    }
    __syncthreads();
    float acc[64];
#pragma unroll
    for (int e = 0; e < 64; e++) acc[e] = 0.f;
    const float* wrow = w_in + (size_t)(1024 + i) * 1024 + dc * 128;
    for (int d4 = 0; d4 < 32; d4++) {
        float4 w4 = reinterpret_cast<const float4*>(wrow)[d4];
#pragma unroll
        for (int e = 0; e < 64; e++) {
            float4 e4 = *reinterpret_cast<const float4*>(&es[e][d4 * 4]);
            acc[e] = fmaf(w4.x, e4.x, acc[e]);
            acc[e] = fmaf(w4.y, e4.y, acc[e]);
            acc[e] = fmaf(w4.z, e4.z, acc[e]);
            acc[e] = fmaf(w4.w, e4.w, acc[e]);
        }
    }
#pragma unroll
    for (int e = 0; e < 64; e++) g_kvpart[dc][e * 2048 + i] = acc[e];
}

// kv[e][i] = sum_dc part + bias   (grid 512, 256 thr)
__global__ void kv_reduce_kernel(const float* __restrict__ b_in) {
    int idx = blockIdx.x * 256 + threadIdx.x;  // [0, 131072)
    int i = idx & 2047;
    float s = 0.f;
#pragma unroll
    for (int dc = 0; dc < 8; dc++) s += g_kvpart[dc][idx];
    g_kv[idx] = s + b_in[1024 + i];
}

// generic transpose: src (R x C) -> dst (C x R); block (32,8)
__global__ void transpose_kernel(const float* __restrict__ src, float* __restrict__ dst,
                                 int R, int C) {
    __shared__ float t[32][33];
    int c0 = blockIdx.x * 32, r0 = blockIdx.y * 32;
    int x = threadIdx.x, y = threadIdx.y;
#pragma unroll
    for (int j = 0; j < 32; j += 8) {
        int r = r0 + y + j, c = c0 + x;
        if (r < R && c < C) t[y + j][x] = src[(size_t)r * C + c];
    }
    __syncthreads();
#pragma unroll
    for (int j = 0; j < 32; j += 8) {
        int r = c0 + y + j, c = r0 + x;
        if (r < C && c < R) dst[(size_t)r * R + c] = t[x][y + j];
    }
}

// Wscore[d][h*64+e] = 0.125 * sum_{d'<64} in_proj_w[h*64+d'][d] * k[e][h*64+d']
// grid (8 dtile, 16 h), 256 thr
__global__ void p1_kernel(const float* __restrict__ w_in) {
    int h = blockIdx.y;
    int d0 = blockIdx.x * 128;
    __shared__ float wq_s[64][128];   // [d'][d_local]
    __shared__ float kq_s[64][64];    // [e][d']
    for (int idx = threadIdx.x; idx < 64 * 32; idx += 256) {
        int row = idx >> 5, c4 = idx & 31;
        float4 v = reinterpret_cast<const float4*>(w_in + (size_t)(h * 64 + row) * 1024 + d0)[c4];
        *reinterpret_cast<float4*>(&wq_s[row][c4 * 4]) = v;
    }
    for (int idx = threadIdx.x; idx < 64 * 16; idx += 256) {
        int e = idx >> 4, c4 = idx & 15;
        float4 v = reinterpret_cast<const float4*>(g_kv + e * 2048 + h * 64)[c4];
        *reinterpret_cast<float4*>(&kq_s[e][c4 * 4]) = v;
    }
    __syncthreads();
    int tx = threadIdx.x & 127, ez = threadIdx.x >> 7;
    float acc[32];
#pragma unroll
    for (int e = 0; e < 32; e++) acc[e] = 0.f;
    for (int dp = 0; dp < 64; dp++) {
        float w = wq_s[dp][tx];
#pragma unroll
        for (int e = 0; e < 32; e++) acc[e] = fmaf(w, kq_s[ez * 32 + e][dp], acc[e]);
    }
#pragma unroll
    for (int e = 0; e < 32; e++)
        g_Wscore[(size_t)(d0 + tx) * 1024 + h * 64 + ez * 32 + e] = acc[e] * 0.125f;
}

// cvec[h*64+e] = 0.125 * sum_{d'} bq[h*64+d'] * k[e][h*64+d']   (grid 4, 256 thr)
__global__ void cvec_kernel(const float* __restrict__ b_in) {
    int he = blockIdx.x * 256 + threadIdx.x;
    int h = he >> 6, e = he & 63;
    float s = 0.f;
    for (int dp = 0; dp < 64; dp++) s += b_in[h * 64 + dp] * g_kv[e * 2048 + h * 64 + dp];
    g_cvec[he] = s * 0.125f;
}

// Bmat[h*64+e][dout] = sum_{d'<64} v[e][h*64+d'] * out_proj_w[dout][h*64+d']
// grid (8 dout-tile, 16 h), 256 thr
__global__ void p2_kernel(const float* __restrict__ w_out) {
    int h = blockIdx.y;
    int n0 = blockIdx.x * 128;
    __shared__ float wo_s[64][128];   // [d'][dout_local]
    __shared__ float v_s[64][64];     // [e][d']
    for (int idx = threadIdx.x; idx < 128 * 16; idx += 256) {
        int r = idx >> 4, c4 = idx & 15;
        float4 v = reinterpret_cast<const float4*>(w_out + (size_t)(n0 + r) * 1024 + h * 64)[c4];
        wo_s[c4 * 4 + 0][r] = v.x;
        wo_s[c4 * 4 + 1][r] = v.y;
        wo_s[c4 * 4 + 2][r] = v.z;
        wo_s[c4 * 4 + 3][r] = v.w;
    }
    for (int idx = threadIdx.x; idx < 64 * 16; idx += 256) {
        int e = idx >> 4, c4 = idx & 15;
        float4 v = reinterpret_cast<const float4*>(g_kv + e * 2048 + 1024 + h * 64)[c4];
        *reinterpret_cast<float4*>(&v_s[e][c4 * 4]) = v;
    }
    __syncthreads();
    int tx = threadIdx.x & 127, ez = threadIdx.x >> 7;
    float acc[32];
#pragma unroll
    for (int e = 0; e < 32; e++) acc[e] = 0.f;
    for (int dp = 0; dp < 64; dp++) {
        float w = wo_s[dp][tx];
#pragma unroll
        for (int e = 0; e < 32; e++) acc[e] = fmaf(w, v_s[ez * 32 + e][dp], acc[e]);
    }
#pragma unroll
    for (int e = 0; e < 32; e++)
        g_Bmat[(size_t)(h * 64 + ez * 32 + e) * 1024 + n0 + tx] = acc[e];
}

// ---------------- main SGEMM: C[M,N] = X[M,K] @ W[K,N] + bias (+gelu) ----------------
// BM=BN=128, BK=8, 256 threads, 8x8 microtile via f32x2 FFMA2, register prefetch.
template <bool GELU>
__global__ void __launch_bounds__(256, 2)
sgemm_kernel(const float* __restrict__ Xp, const float* __restrict__ Wp,
             const float* __restrict__ bias, float* __restrict__ Cp,
             int M, int N, int K) {
    __shared__ float As[8][128];
    __shared__ float Bs[8][128];
    int tid = threadIdx.x;
    int row0 = blockIdx.y * 128, n0 = blockIdx.x * 128;
    int tx = tid & 15, ty = tid >> 4;
    int arow = tid >> 1, ak = (tid & 1) * 4;
    int bk = tid >> 5, bn = (tid & 31) * 4;
    const float* aptr = Xp + (size_t)(row0 + arow) * K + ak;
    const float* bptr = Wp + (size_t)bk * N + n0 + bn;
    float4 aReg = *reinterpret_cast<const float4*>(aptr);
    float4 bReg = *reinterpret_cast<const float4*>(bptr);

    unsigned long long acc[8][4];
#pragma unroll
    for (int r = 0; r < 8; r++)
#pragma unroll
        for (int c = 0; c < 4; c++) acc[r][c] = 0ull;

    int nt = K >> 3;
    for (int kt = 0; kt < nt; kt++) {
        __syncthreads();
        As[ak + 0][arow] = aReg.x;
        As[ak + 1][arow] = aReg.y;
        As[ak + 2][arow] = aReg.z;
        As[ak + 3][arow] = aReg.w;
        *reinterpret_cast<float4*>(&Bs[bk][bn]) = bReg;
        __syncthreads();
        if (kt + 1 < nt) {
            aReg = *reinterpret_cast<const float4*>(aptr + (kt + 1) * 8);
            bReg = *reinterpret_cast<const float4*>(bptr + (size_t)(kt + 1) * 8 * N);
        }
#pragma unroll
        for (int k = 0; k < 8; k++) {
            float4 a0 = *reinterpret_cast<const float4*>(&As[k][ty * 8]);
            float4 a1 = *reinterpret_cast<const float4*>(&As[k][ty * 8 + 4]);
            ulonglong2 b0 = *reinterpret_cast<const ulonglong2*>(&Bs[k][tx * 8]);
            ulonglong2 b1 = *reinterpret_cast<const ulonglong2*>(&Bs[k][tx * 8 + 4]);
            unsigned long long bp0 = b0.x, bp1 = b0.y, bp2 = b1.x, bp3 = b1.y;
            float av[8] = {a0.x, a0.y, a0.z, a0.w, a1.x, a1.y, a1.z, a1.w};
#pragma unroll
            for (int r = 0; r < 8; r++) {
                unsigned long long ar = pk2(av[r], av[r]);
                acc[r][0] = ffma2(ar, bp0, acc[r][0]);
                acc[r][1] = ffma2(ar, bp1, acc[r][1]);
                acc[r][2] = ffma2(ar, bp2, acc[r][2]);
                acc[r][3] = ffma2(ar, bp3, acc[r][3]);
            }
        }
    }

    int nb = n0 + tx * 8;
    float bv[8];
#pragma unroll
    for (int j = 0; j < 8; j++) bv[j] = bias[nb + j];
#pragma unroll
    for (int r = 0; r < 8; r++) {
        int m = row0 + ty * 8 + r;
        float o[8];
#pragma unroll
        for (int c = 0; c < 4; c++) {
            float lo, hi;
            upk2(acc[r][c], lo, hi);
            o[2 * c] = lo;
            o[2 * c + 1] = hi;
        }
#pragma unroll
        for (int j = 0; j < 8; j++) {
            float v = o[j] + bv[j];
            if (GELU) v = gelu_exact(v);
            o[j] = v;
        }
        *reinterpret_cast<float4*>(&Cp[(size_t)m * N + nb]) = make_float4(o[0], o[1], o[2], o[3]);
        *reinterpret_cast<float4*>(&Cp[(size_t)m * N + nb + 4]) = make_float4(o[4], o[5], o[6], o[7]);
    }
}

// ---------------- attention softmax over E=64 per (token, head); in place on g_S ----------------
// grid 32768, 256 thr (8 warps; one warp per (t,h))
__global__ void attn_softmax_kernel() {
    int gw = blockIdx.x * 8 + (threadIdx.x >> 5);
    int lane = threadIdx.x & 31;
    int t = gw >> 4, h = gw & 15;
    float* p = g_S + (size_t)t * 1024 + h * 64;
    float v0 = p[lane], v1 = p[lane + 32];
    float m = fmaxf(v0, v1);
#pragma unroll
    for (int s = 16; s; s >>= 1) m = fmaxf(m, __shfl_xor_sync(0xffffffffu, m, s));
    float e0 = expf(v0 - m), e1 = expf(v1 - m);
    float s = e0 + e1;
#pragma unroll
    for (int sh = 16; sh; sh >>= 1) s += __shfl_xor_sync(0xffffffffu, s, sh);
    float inv = 1.0f / s;
    p[lane] = e0 * inv;
    p[lane + 32] = e1 * inv;
}

// ---------------- gate logits + softmax + top2 ----------------
// grid NTOK, 64 threads (one expert each)
__global__ void final_kernel(const float* __restrict__ b2, float* __restrict__ out) {
    int t = blockIdx.x;
    int e = threadIdx.x;
    __shared__ float hs[256];
    __shared__ float red[64];
    __shared__ int redi[64];
    for (int j = e; j < 256; j += 64) hs[j] = g_Hb[(size_t)t * 256 + j];
    __syncthreads();
    float acc = b2[e];
#pragma unroll 8
    for (int j = 0; j < 256; j++) acc = fmaf(hs[j], g_w2t[j * 64 + e], acc);
    // softmax(64)
    red[e] = acc;
    __syncthreads();
    for (int s = 32; s; s >>= 1) {
        if (e < s) red[e] = fmaxf(red[e], red[e + s]);
        __syncthreads();
    }
    float m = red[0];
    __syncthreads();
    float p = expf(acc - m);
    red[e] = p;
    __syncthreads();
    for (int s = 32; s; s >>= 1) {
        if (e < s) red[e] += red[e + s];
        __syncthreads();
    }
    float prob = p / red[0];
    __syncthreads();
    // top-1 (ties -> lower index, matching lax.top_k)
    red[e] = prob;
    redi[e] = e;
    __syncthreads();
    for (int s = 32; s; s >>= 1) {
        if (e < s) {
            float ov = red[e + s];
            int oi = redi[e + s];
            if (ov > red[e] || (ov == red[e] && oi < redi[e])) { red[e] = ov; redi[e] = oi; }
        }
        __syncthreads();
    }
    float v1 = red[0];
    int i1 = redi[0];
    __syncthreads();
    // top-2
    red[e] = (e == i1) ? -1.0f : prob;
    redi[e] = e;
    __syncthreads();
    for (int s = 32; s; s >>= 1) {
        if (e < s) {
            float ov = red[e + s];
            int oi = redi[e + s];
            if (ov > red[e] || (ov == red[e] && oi < redi[e])) { red[e] = ov; redi[e] = oi; }
        }
        __syncthreads();
    }
    if (e == 0) {
        float v2 = red[0];
        int i2 = redi[0];
        float denom = v1 + v2 + 1e-8f;
        // output layout: [idx (B,S,K) as float | weights (B,S,K)]
        out[(size_t)t * 2 + 0] = (float)i1;
        out[(size_t)t * 2 + 1] = (float)i2;
        out[(size_t)NTOK * 2 + (size_t)t * 2 + 0] = v1 / denom;
        out[(size_t)NTOK * 2 + (size_t)t * 2 + 1] = v2 / denom;
    }
}

// ---------------- launch ----------------
extern "C" void kernel_launch(void* const* d_in, const int* in_sizes, int n_in,
                              void* d_out, int out_size) {
    (void)in_sizes; (void)n_in; (void)out_size;
    const float* x     = (const float*)d_in[0];
    const float* emb   = (const float*)d_in[1];
    const float* w_in  = (const float*)d_in[2];
    const float* b_in  = (const float*)d_in[3];
    const float* w_out = (const float*)d_in[4];
    const float* b_out = (const float*)d_in[5];
    const float* w1    = (const float*)d_in[6];
    const float* b1    = (const float*)d_in[7];
    const float* w2    = (const float*)d_in[8];
    const float* b2    = (const float*)d_in[9];
    float* out = (float*)d_out;

    float *pS, *pP, *pHb, *pWs, *pB, *pc, *pw1t, *pw2t;
    cudaGetSymbolAddress((void**)&pS, g_S);
    cudaGetSymbolAddress((void**)&pP, g_P);
    cudaGetSymbolAddress((void**)&pHb, g_Hb);
    cudaGetSymbolAddress((void**)&pWs, g_Wscore);
    cudaGetSymbolAddress((void**)&pB, g_Bmat);
    cudaGetSymbolAddress((void**)&pc, g_cvec);
    cudaGetSymbolAddress((void**)&pw1t, g_w1t);
    cudaGetSymbolAddress((void**)&pw2t, g_w2t);

    // precompute fused weights
    kv_part_kernel<<<dim3(8, 8), 256>>>(w_in, emb);
    kv_reduce_kernel<<<512, 256>>>(b_in);
    transpose_kernel<<<dim3(32, 8), dim3(32, 8)>>>(w1, pw1t, 256, 1024);
    transpose_kernel<<<dim3(8, 2), dim3(32, 8)>>>(w2, pw2t, 64, 256);
    p1_kernel<<<dim3(8, 16), 256>>>(w_in);
    cvec_kernel<<<4, 256>>>(b_in);
    p2_kernel<<<dim3(8, 16), 256>>>(w_out);

    // scores = x @ Wscore + c
    sgemm_kernel<false><<<dim3(8, 128), 256>>>(x, pWs, pc, pS, NTOK, 1024, 1024);
    // per-(t,h) softmax over 64 experts
    attn_softmax_kernel<<<32768, 256>>>();
    // attn_out = attn @ Bmat + b_out
    sgemm_kernel<false><<<dim3(8, 128), 256>>>(pS, pB, b_out, pP, NTOK, 1024, 1024);
    // hidden = gelu(attn_out @ w1^T + b1)
    sgemm_kernel<true><<<dim3(2, 128), 256>>>(pP, pw1t, b1, pHb, NTOK, 256, 1024);
    // logits + softmax + top2 + weights
    final_kernel<<<NTOK, 64>>>(b2, out);
}

// round 5
// speedup vs baseline: 2.3963x; 2.3963x over previous
#include <cuda_runtime.h>
#include <cuda_fp16.h>
#include <math.h>
#include <stdint.h>

#define NTOK 16384
#define DM 1024
typedef __half h16;

// ---------------- scratch (static device globals) ----------------
__device__ float g_kvpart[8][64 * 2048];
__device__ float g_kv[64 * 2048];
__device__ float g_cvec[1024];
__device__ float g_w2t[256 * 64];
__device__ float g_Hb[(size_t)NTOK * 256];

__device__ h16 g_Xhi[(size_t)NTOK * DM], g_Xlo[(size_t)NTOK * DM];
__device__ h16 g_Shi[(size_t)NTOK * DM], g_Slo[(size_t)NTOK * DM];
__device__ h16 g_Phi[(size_t)NTOK * DM], g_Plo[(size_t)NTOK * DM];
__device__ h16 g_Wshi[1024 * 1024], g_Wslo[1024 * 1024];
__device__ h16 g_Bmhi[1024 * 1024], g_Bmlo[1024 * 1024];
__device__ h16 g_W1hi[256 * 1024], g_W1lo[256 * 1024];

// ---------------- helpers ----------------
__device__ __forceinline__ uint32_t smem_u32(const void* p) {
    uint32_t a;
    asm("{ .reg .u64 t; cvta.to.shared.u64 t, %1; cvt.u32.u64 %0, t; }" : "=r"(a) : "l"(p));
    return a;
}
__device__ __forceinline__ void split2(float v, h16& hh, h16& ll) {
    hh = __float2half_rn(v);
    ll = __float2half_rn(v - __half2float(hh));
}
__device__ __forceinline__ uint32_t pkh(h16 a, h16 b) {
    __half2 t = __halves2half2(a, b);
    return *reinterpret_cast<uint32_t*>(&t);
}
__device__ __forceinline__ float gelu_exact(float x) {
    return 0.5f * x * (1.0f + erff(x * 0.70710678118654752f));
}

#define LDSM4(r, a)                                                               \
    asm volatile("ldmatrix.sync.aligned.m8n8.x4.shared.b16 {%0,%1,%2,%3}, [%4];"  \
                 : "=r"((r)[0]), "=r"((r)[1]), "=r"((r)[2]), "=r"((r)[3]) : "r"(a))

#define MMA16816(c, a, b)                                                         \
    asm volatile("mma.sync.aligned.m16n8k16.row.col.f32.f16.f16.f32 "             \
                 "{%0,%1,%2,%3},{%4,%5,%6,%7},{%8,%9},{%0,%1,%2,%3};"             \
                 : "+f"((c)[0]), "+f"((c)[1]), "+f"((c)[2]), "+f"((c)[3])         \
                 : "r"((a)[0]), "r"((a)[1]), "r"((a)[2]), "r"((a)[3]),            \
                   "r"((b)[0]), "r"((b)[1]))

#define CP16(d, s) \
    asm volatile("cp.async.cg.shared.global [%0], [%1], 16;" :: "r"(d), "l"(s))
#define CP_COMMIT() asm volatile("cp.async.commit_group;")
#define CP_WAIT1() asm volatile("cp.async.wait_group 1;")
#define CP_WAIT0() asm volatile("cp.async.wait_group 0;")

// ---------------- elementwise split ----------------
__global__ void split_kernel(const float* __restrict__ src, h16* __restrict__ hp,
                             h16* __restrict__ lp) {
    int i = blockIdx.x * 256 + threadIdx.x;
    float4 v = reinterpret_cast<const float4*>(src)[i];
    h16 h0, l0, h1, l1, h2, l2, h3, l3;
    split2(v.x, h0, l0); split2(v.y, h1, l1);
    split2(v.z, h2, l2); split2(v.w, h3, l3);
    reinterpret_cast<uint2*>(hp)[i] = make_uint2(pkh(h0, h1), pkh(h2, h3));
    reinterpret_cast<uint2*>(lp)[i] = make_uint2(pkh(l0, l1), pkh(l2, l3));
}

// ---------------- precompute ----------------
__global__ void kv_part_kernel(const float* __restrict__ w_in, const float* __restrict__ emb) {
    int ic = blockIdx.x, dc = blockIdx.y;
    int i = ic * 256 + threadIdx.x;
    __shared__ float es[64][132];
    for (int idx = threadIdx.x; idx < 64 * 128; idx += 256) {
        int e = idx >> 7, dl = idx & 127;
        es[e][dl] = emb[e * 1024 + dc * 128 + dl];
    }
    __syncthreads();
    float acc[64];
#pragma unroll
    for (int e = 0; e < 64; e++) acc[e] = 0.f;
    const float* wrow = w_in + (size_t)(1024 + i) * 1024 + dc * 128;
    for (int d4 = 0; d4 < 32; d4++) {
        float4 w4 = reinterpret_cast<const float4*>(wrow)[d4];
#pragma unroll
        for (int e = 0; e < 64; e++) {
            float4 e4 = *reinterpret_cast<const float4*>(&es[e][d4 * 4]);
            acc[e] = fmaf(w4.x, e4.x, acc[e]);
            acc[e] = fmaf(w4.y, e4.y, acc[e]);
            acc[e] = fmaf(w4.z, e4.z, acc[e]);
            acc[e] = fmaf(w4.w, e4.w, acc[e]);
        }
    }
#pragma unroll
    for (int e = 0; e < 64; e++) g_kvpart[dc][e * 2048 + i] = acc[e];
}

__global__ void kv_reduce_kernel(const float* __restrict__ b_in) {
    int idx = blockIdx.x * 256 + threadIdx.x;
    int i = idx & 2047;
    float s = 0.f;
#pragma unroll
    for (int dc = 0; dc < 8; dc++) s += g_kvpart[dc][idx];
    g_kv[idx] = s + b_in[1024 + i];
}

__global__ void transpose_kernel(const float* __restrict__ src, float* __restrict__ dst,
                                 int R, int C) {
    __shared__ float t[32][33];
    int c0 = blockIdx.x * 32, r0 = blockIdx.y * 32;
    int x = threadIdx.x, y = threadIdx.y;
#pragma unroll
    for (int j = 0; j < 32; j += 8) {
        int r = r0 + y + j, c = c0 + x;
        if (r < R && c < C) t[y + j][x] = src[(size_t)r * C + c];
    }
    __syncthreads();
#pragma unroll
    for (int j = 0; j < 32; j += 8) {
        int r = c0 + y + j, c = r0 + x;
        if (r < C && c < R) dst[(size_t)r * R + c] = t[x][y + j];
    }
}

// Wscore planes [he][d]
__global__ void p1_kernel(const float* __restrict__ w_in) {
    int h = blockIdx.y;
    int d0 = blockIdx.x * 128;
    __shared__ float wq_s[64][128];
    __shared__ float kq_s[64][64];
    for (int idx = threadIdx.x; idx < 64 * 32; idx += 256) {
        int row = idx >> 5, c4 = idx & 31;
        float4 v = reinterpret_cast<const float4*>(w_in + (size_t)(h * 64 + row) * 1024 + d0)[c4];
        *reinterpret_cast<float4*>(&wq_s[row][c4 * 4]) = v;
    }
    for (int idx = threadIdx.x; idx < 64 * 16; idx += 256) {
        int e = idx >> 4, c4 = idx & 15;
        float4 v = reinterpret_cast<const float4*>(g_kv + e * 2048 + h * 64)[c4];
        *reinterpret_cast<float4*>(&kq_s[e][c4 * 4]) = v;
    }
    __syncthreads();
    int tx = threadIdx.x & 127, ez = threadIdx.x >> 7;
    float acc[32];
#pragma unroll
    for (int e = 0; e < 32; e++) acc[e] = 0.f;
    for (int dp = 0; dp < 64; dp++) {
        float w = wq_s[dp][tx];
#pragma unroll
        for (int e = 0; e < 32; e++) acc[e] = fmaf(w, kq_s[ez * 32 + e][dp], acc[e]);
    }
#pragma unroll
    for (int e = 0; e < 32; e++) {
        size_t idx = (size_t)(h * 64 + ez * 32 + e) * 1024 + d0 + tx;
        h16 a, b;
        split2(acc[e] * 0.125f, a, b);
        g_Wshi[idx] = a; g_Wslo[idx] = b;
    }
}

__global__ void cvec_kernel(const float* __restrict__ b_in) {
    int he = blockIdx.x * 256 + threadIdx.x;
    int h = he >> 6, e = he & 63;
    float s = 0.f;
    for (int dp = 0; dp < 64; dp++) s += b_in[h * 64 + dp] * g_kv[e * 2048 + h * 64 + dp];
    g_cvec[he] = s * 0.125f;
}

// Bmat planes [dout][he]
__global__ void p2_kernel(const float* __restrict__ w_out) {
    int h = blockIdx.y;
    int n0 = blockIdx.x * 128;
    __shared__ float wo_s[64][128];
    __shared__ float v_s[64][64];
    for (int idx = threadIdx.x; idx < 128 * 16; idx += 256) {
        int r = idx >> 4, c4 = idx & 15;
        float4 v = reinterpret_cast<const float4*>(w_out + (size_t)(n0 + r) * 1024 + h * 64)[c4];
        wo_s[c4 * 4 + 0][r] = v.x;
        wo_s[c4 * 4 + 1][r] = v.y;
        wo_s[c4 * 4 + 2][r] = v.z;
        wo_s[c4 * 4 + 3][r] = v.w;
    }
    for (int idx = threadIdx.x; idx < 64 * 16; idx += 256) {
        int e = idx >> 4, c4 = idx & 15;
        float4 v = reinterpret_cast<const float4*>(g_kv + e * 2048 + 1024 + h * 64)[c4];
        *reinterpret_cast<float4*>(&v_s[e][c4 * 4]) = v;
    }
    __syncthreads();
    int tx = threadIdx.x & 127, ez = threadIdx.x >> 7;
    float acc[32];
#pragma unroll
    for (int e = 0; e < 32; e++) acc[e] = 0.f;
    for (int dp = 0; dp < 64; dp++) {
        float w = wo_s[dp][tx];
#pragma unroll
        for (int e = 0; e < 32; e++) acc[e] = fmaf(w, v_s[ez * 32 + e][dp], acc[e]);
    }
#pragma unroll
    for (int e = 0; e < 32; e++) {
        size_t idx = (size_t)(n0 + tx) * 1024 + h * 64 + ez * 32 + e;
        h16 a, b;
        split2(acc[e], a, b);
        g_Bmhi[idx] = a; g_Bmlo[idx] = b;
    }
}

// ---------------- mma.sync split GEMM ----------------
// C[M,N] = Ah@Bh^T + Ah@Bl^T + Al@Bh^T   (A [M][K], B [N][K], K=1024)
// BM=BN=128, BK=64 halves, 256 thr, 2-stage cp.async, warp tile 64x32.
// MODE 0: +bias, softmax per 64-col head, split-write 2 fp16 planes
// MODE 1: +bias, split-write 2 fp16 planes
// MODE 2: +bias, gelu, fp32 write (NOUT cols total)
#define PLANE_B 16384         // 128 rows * 128 bytes
#define STAGE_B (4 * PLANE_B) // Ah, Al, Bh, Bl
#define GEMM_SMEM (2 * STAGE_B)

template <int MODE, int NOUT>
__global__ void __launch_bounds__(256, 1)
gemm_mma(const h16* __restrict__ Ah, const h16* __restrict__ Al,
         const h16* __restrict__ Bh, const h16* __restrict__ Bl,
         const float* __restrict__ bias,
         h16* __restrict__ Ohi, h16* __restrict__ Olo, float* __restrict__ Of) {
    extern __shared__ char smem[];
    const uint32_t sb = smem_u32(smem);
    const int tid = threadIdx.x, lane = tid & 31, w = tid >> 5;
    const int wm = w >> 2, wn = w & 3;          // warp grid 2 x 4 (64 x 32 tiles)
    const int m0 = blockIdx.y * 128, n0 = blockIdx.x * 128;

    const h16* pb[4] = {Ah + (size_t)m0 * 1024, Al + (size_t)m0 * 1024,
                        Bh + (size_t)n0 * 1024, Bl + (size_t)n0 * 1024};

    auto load_tile = [&](int kt, int s) {
        uint32_t sbase = sb + s * STAGE_B;
#pragma unroll
        for (int p = 0; p < 4; p++) {
            const h16* src = pb[p] + kt * 64;
#pragma unroll
            for (int j = 0; j < 4; j++) {
                int gid = tid + 256 * j;             // 0..1023
                int row = gid >> 3;
                int ch = gid & 7;
                const h16* g = src + (size_t)row * 1024 + ch * 8;
                uint32_t d = sbase + p * PLANE_B + row * 128 + ((ch ^ (row & 7)) << 4);
                CP16(d, g);
            }
        }
        CP_COMMIT();
    };

    load_tile(0, 0);
    load_tile(1, 1);

    float acc[4][4][4];
#pragma unroll
    for (int mt = 0; mt < 4; mt++)
#pragma unroll
        for (int nt = 0; nt < 4; nt++)
#pragma unroll
            for (int r = 0; r < 4; r++) acc[mt][nt][r] = 0.f;

    const int gq = lane >> 3, li = lane & 7;

    for (int kt = 0; kt < 16; kt++) {
        CP_WAIT1();
        __syncthreads();
        uint32_t sbase = sb + (kt & 1) * STAGE_B;
#pragma unroll
        for (int ks = 0; ks < 4; ks++) {
            uint32_t af[2][4][4];
            uint32_t bf[2][4][2];
#pragma unroll
            for (int p = 0; p < 2; p++) {
#pragma unroll
                for (int mt = 0; mt < 4; mt++) {
                    int row = wm * 64 + mt * 16 + ((gq & 1) << 3) + li;
                    int kc = ks * 2 + (gq >> 1);
                    uint32_t ad = sbase + p * PLANE_B + row * 128 + ((kc ^ (row & 7)) << 4);
                    LDSM4(af[p][mt], ad);
                }
            }
#pragma unroll
            for (int p = 0; p < 2; p++) {
#pragma unroll
                for (int np = 0; np < 2; np++) {
                    int row = wn * 32 + np * 16 + ((gq >> 1) << 3) + li;
                    int kc = ks * 2 + (gq & 1);
                    uint32_t ad = sbase + (2 + p) * PLANE_B + row * 128 + ((kc ^ (row & 7)) << 4);
                    uint32_t r4[4];
                    LDSM4(r4, ad);
                    bf[p][np * 2][0] = r4[0]; bf[p][np * 2][1] = r4[1];
                    bf[p][np * 2 + 1][0] = r4[2]; bf[p][np * 2 + 1][1] = r4[3];
                }
            }
#pragma unroll
            for (int mt = 0; mt < 4; mt++)
#pragma unroll
                for (int nt = 0; nt < 4; nt++) {
                    MMA16816(acc[mt][nt], af[0][mt], bf[0][nt]);  // hi*hi
                    MMA16816(acc[mt][nt], af[0][mt], bf[1][nt]);  // hi*lo
                    MMA16816(acc[mt][nt], af[1][mt], bf[0][nt]);  // lo*hi
                }
        }
        __syncthreads();
        if (kt + 2 < 16) load_tile(kt + 2, kt & 1);
    }
    CP_WAIT0();
    __syncthreads();

    // ---- epilogue: stage C in smem so each thread owns a 64-col row segment ----
    float* Cs = reinterpret_cast<float*>(smem);
    const int P = 130;
#pragma unroll
    for (int mt = 0; mt < 4; mt++)
#pragma unroll
        for (int nt = 0; nt < 4; nt++) {
            int m = wm * 64 + mt * 16 + (lane >> 2);
            int n = wn * 32 + nt * 8 + ((lane & 3) << 1);
            *reinterpret_cast<float2*>(&Cs[m * P + n]) =
                make_float2(acc[mt][nt][0], acc[mt][nt][1]);
            *reinterpret_cast<float2*>(&Cs[(m + 8) * P + n]) =
                make_float2(acc[mt][nt][2], acc[mt][nt][3]);
        }
    __syncthreads();

    int r = tid >> 1, seg = tid & 1;
    float v[64];
#pragma unroll
    for (int c = 0; c < 64; c++)
        v[c] = Cs[r * P + seg * 64 + c] + __ldg(bias + n0 + seg * 64 + c);

    if (MODE == 0) {
        float mx = v[0];
#pragma unroll
        for (int c = 1; c < 64; c++) mx = fmaxf(mx, v[c]);
        float s = 0.f;
#pragma unroll
        for (int c = 0; c < 64; c++) { v[c] = expf(v[c] - mx); s += v[c]; }
        float inv = 1.0f / s;
#pragma unroll
        for (int c = 0; c < 64; c++) v[c] *= inv;
    }

    if (MODE == 2) {
        size_t o = (size_t)(m0 + r) * NOUT + n0 + seg * 64;
#pragma unroll
        for (int c = 0; c < 64; c += 4)
            *reinterpret_cast<float4*>(Of + o + c) =
                make_float4(gelu_exact(v[c]), gelu_exact(v[c + 1]),
                            gelu_exact(v[c + 2]), gelu_exact(v[c + 3]));
    } else {
        size_t o = (size_t)(m0 + r) * 1024 + n0 + seg * 64;
#pragma unroll
        for (int c0 = 0; c0 < 64; c0 += 8) {
            uint32_t hw[4], lw[4];
#pragma unroll
            for (int j = 0; j < 4; j++) {
                h16 a, b, c, d;
                split2(v[c0 + 2 * j], a, b);
                split2(v[c0 + 2 * j + 1], c, d);
                hw[j] = pkh(a, c);
                lw[j] = pkh(b, d);
            }
            *reinterpret_cast<uint4*>(Ohi + o + c0) = make_uint4(hw[0], hw[1], hw[2], hw[3]);
            *reinterpret_cast<uint4*>(Olo + o + c0) = make_uint4(lw[0], lw[1], lw[2], lw[3]);
        }
    }
}

// ---------------- gate logits + softmax + top2 ----------------
__global__ void final_kernel(const float* __restrict__ b2, float* __restrict__ out) {
    int t = blockIdx.x;
    int e = threadIdx.x;
    __shared__ float hs[256];
    __shared__ float red[64];
    __shared__ int redi[64];
    for (int j = e; j < 256; j += 64) hs[j] = g_Hb[(size_t)t * 256 + j];
    __syncthreads();
    float acc = b2[e];
#pragma unroll 8
    for (int j = 0; j < 256; j++) acc = fmaf(hs[j], g_w2t[j * 64 + e], acc);
    red[e] = acc;
    __syncthreads();
    for (int s = 32; s; s >>= 1) {
        if (e < s) red[e] = fmaxf(red[e], red[e + s]);
        __syncthreads();
    }
    float m = red[0];
    __syncthreads();
    float p = expf(acc - m);
    red[e] = p;
    __syncthreads();
    for (int s = 32; s; s >>= 1) {
        if (e < s) red[e] += red[e + s];
        __syncthreads();
    }
    float prob = p / red[0];
    __syncthreads();
    red[e] = prob;
    redi[e] = e;
    __syncthreads();
    for (int s = 32; s; s >>= 1) {
        if (e < s) {
            float ov = red[e + s]; int oi = redi[e + s];
            if (ov > red[e] || (ov == red[e] && oi < redi[e])) { red[e] = ov; redi[e] = oi; }
        }
        __syncthreads();
    }
    float v1 = red[0]; int i1 = redi[0];
    __syncthreads();
    red[e] = (e == i1) ? -1.0f : prob;
    redi[e] = e;
    __syncthreads();
    for (int s = 32; s; s >>= 1) {
        if (e < s) {
            float ov = red[e + s]; int oi = redi[e + s];
            if (ov > red[e] || (ov == red[e] && oi < redi[e])) { red[e] = ov; redi[e] = oi; }
        }
        __syncthreads();
    }
    if (e == 0) {
        float v2 = red[0]; int i2 = redi[0];
        float denom = v1 + v2 + 1e-8f;
        out[(size_t)t * 2 + 0] = (float)i1;
        out[(size_t)t * 2 + 1] = (float)i2;
        out[(size_t)NTOK * 2 + (size_t)t * 2 + 0] = v1 / denom;
        out[(size_t)NTOK * 2 + (size_t)t * 2 + 1] = v2 / denom;
    }
}

// ---------------- launch ----------------
extern "C" void kernel_launch(void* const* d_in, const int* in_sizes, int n_in,
                              void* d_out, int out_size) {
    (void)in_sizes; (void)n_in; (void)out_size;
    const float* x     = (const float*)d_in[0];
    const float* emb   = (const float*)d_in[1];
    const float* w_in  = (const float*)d_in[2];
    const float* b_in  = (const float*)d_in[3];
    const float* w_out = (const float*)d_in[4];
    const float* b_out = (const float*)d_in[5];
    const float* w1    = (const float*)d_in[6];
    const float* b1    = (const float*)d_in[7];
    const float* w2    = (const float*)d_in[8];
    const float* b2    = (const float*)d_in[9];
    float* out = (float*)d_out;

    float *pc, *pw2t, *pHb;
    h16 *pXhi, *pXlo, *pShi, *pSlo, *pPhi, *pPlo;
    h16 *pWshi, *pWslo, *pBmhi, *pBmlo, *pW1hi, *pW1lo;
    cudaGetSymbolAddress((void**)&pc, g_cvec);
    cudaGetSymbolAddress((void**)&pw2t, g_w2t);
    cudaGetSymbolAddress((void**)&pHb, g_Hb);
    cudaGetSymbolAddress((void**)&pXhi, g_Xhi);   cudaGetSymbolAddress((void**)&pXlo, g_Xlo);
    cudaGetSymbolAddress((void**)&pShi, g_Shi);   cudaGetSymbolAddress((void**)&pSlo, g_Slo);
    cudaGetSymbolAddress((void**)&pPhi, g_Phi);   cudaGetSymbolAddress((void**)&pPlo, g_Plo);
    cudaGetSymbolAddress((void**)&pWshi, g_Wshi); cudaGetSymbolAddress((void**)&pWslo, g_Wslo);
    cudaGetSymbolAddress((void**)&pBmhi, g_Bmhi); cudaGetSymbolAddress((void**)&pBmlo, g_Bmlo);
    cudaGetSymbolAddress((void**)&pW1hi, g_W1hi); cudaGetSymbolAddress((void**)&pW1lo, g_W1lo);

    cudaFuncSetAttribute(gemm_mma<0, 1024>, cudaFuncAttributeMaxDynamicSharedMemorySize, GEMM_SMEM);
    cudaFuncSetAttribute(gemm_mma<1, 1024>, cudaFuncAttributeMaxDynamicSharedMemorySize, GEMM_SMEM);
    cudaFuncSetAttribute(gemm_mma<2, 256>,  cudaFuncAttributeMaxDynamicSharedMemorySize, GEMM_SMEM);

    // input splits
    split_kernel<<<(NTOK * DM / 4) / 256, 256>>>(x, pXhi, pXlo);
    split_kernel<<<(256 * 1024 / 4) / 256, 256>>>(w1, pW1hi, pW1lo);

    // fused-weight precompute
    kv_part_kernel<<<dim3(8, 8), 256>>>(w_in, emb);
    kv_reduce_kernel<<<512, 256>>>(b_in);
    transpose_kernel<<<dim3(8, 2), dim3(32, 8)>>>(w2, pw2t, 64, 256);
    p1_kernel<<<dim3(8, 16), 256>>>(w_in);
    cvec_kernel<<<4, 256>>>(b_in);
    p2_kernel<<<dim3(8, 16), 256>>>(w_out);

    // scores -> softmax -> attn planes
    gemm_mma<0, 1024><<<dim3(8, 128), 256, GEMM_SMEM>>>(
        pXhi, pXlo, pWshi, pWslo, pc, pShi, pSlo, nullptr);
    // attn_out planes
    gemm_mma<1, 1024><<<dim3(8, 128), 256, GEMM_SMEM>>>(
        pShi, pSlo, pBmhi, pBmlo, b_out, pPhi, pPlo, nullptr);
    // gate hidden (gelu) fp32
    gemm_mma<2, 256><<<dim3(2, 128), 256, GEMM_SMEM>>>(
        pPhi, pPlo, pW1hi, pW1lo, b1, nullptr, nullptr, pHb);
    // logits + softmax + top2
    final_kernel<<<NTOK, 64>>>(b2, out);
}